// round 6
// baseline (speedup 1.0000x reference)
#include <cuda_runtime.h>
#include <math.h>
#include <stdint.h>

// Problem constants
#define BB 8
#define LL 1024
#define HH 16
#define DKK 64
#define DMM 1024
#define BL (BB*LL)          // 8192
#define HBC (HH*BB)         // 128
#define ATTN_OFF ((size_t)BL*DMM)

// Scratch
__device__ float g_qs[(size_t)HBC*LL*DKK];   // (h*B+b, l, dk), q pre-scaled 1/32
__device__ float g_ks[(size_t)HBC*LL*DKK];
__device__ float g_vs[(size_t)HBC*LL*DKK];
__device__ float g_ctx[(size_t)BL*DMM];
__device__ float g_tmp[(size_t)BL*DMM];
__device__ float g_rowsum[(size_t)HBC*LL];

// ---------------------------------------------------------------------------
__device__ __forceinline__ uint32_t f2tf(float f) {
    uint32_t u;
    asm("cvt.rna.tf32.f32 %0, %1;" : "=r"(u) : "f"(f));
    return u;
}

__device__ __forceinline__ void mma8(float* c, const uint32_t* a, const uint32_t* b) {
    asm volatile(
        "mma.sync.aligned.m16n8k8.row.col.f32.tf32.tf32.f32 "
        "{%0,%1,%2,%3},{%4,%5,%6,%7},{%8,%9},{%0,%1,%2,%3};\n"
        : "+f"(c[0]), "+f"(c[1]), "+f"(c[2]), "+f"(c[3])
        : "r"(a[0]), "r"(a[1]), "r"(a[2]), "r"(a[3]), "r"(b[0]), "r"(b[1]));
}

// ===========================================================================
// Kernel 1: QKV projection (tf32 MMA, reg-prefetch double buffering)
// ===========================================================================
__global__ __launch_bounds__(256) void qkv_kernel(
    const float* __restrict__ q, const float* __restrict__ k, const float* __restrict__ v,
    const float* __restrict__ wq, const float* __restrict__ wk, const float* __restrict__ wv)
{
    const int which = blockIdx.z;
    const float* A = (which == 0) ? q : (which == 1) ? k : v;
    const float* W = (which == 0) ? wq : (which == 1) ? wk : wv;
    float* O = (which == 0) ? g_qs : (which == 1) ? g_ks : g_vs;
    const float oscale = (which == 0) ? (1.0f / 32.0f) : 1.0f;

    __shared__ uint32_t As[128][36];
    __shared__ uint32_t Bs[128][36];

    const int m0 = blockIdx.x * 128;
    const int n0 = blockIdx.y * 128;
    const int tid = threadIdx.x;
    const int wid = tid >> 5, lane = tid & 31;
    const int warp_m = (wid & 1) * 64;
    const int warp_n = (wid >> 1) * 32;
    const int grp = lane >> 2, qd = lane & 3;

    const int a_r = tid >> 3;
    const int a_c4 = (tid & 7) * 4;
    const int b_ln4 = (tid & 31) * 4;
    const int b_dr = tid >> 5;
    const int b_h = (n0 + b_ln4) >> 6;
    const int b_kc4 = (n0 + b_ln4) & 63;
    const float* Wp = W + (size_t)b_h * DMM * DKK + b_kc4;

    float acc[4][4][4];
    #pragma unroll
    for (int i = 0; i < 4; i++)
        #pragma unroll
        for (int j = 0; j < 4; j++)
            #pragma unroll
            for (int e = 0; e < 4; e++) acc[i][j][e] = 0.0f;

    float4 a_reg[4], b_reg[4];
    #pragma unroll
    for (int rr = 0; rr < 4; rr++)
        a_reg[rr] = *reinterpret_cast<const float4*>(A + (size_t)(m0 + a_r + rr * 32) * DMM + a_c4);
    #pragma unroll
    for (int kk = 0; kk < 4; kk++)
        b_reg[kk] = *reinterpret_cast<const float4*>(Wp + (size_t)(b_dr + kk * 8) * DKK);

    for (int k0 = 0; k0 < DMM; k0 += 32) {
        #pragma unroll
        for (int rr = 0; rr < 4; rr++) {
            const int r = a_r + rr * 32;
            *reinterpret_cast<uint4*>(&As[r][a_c4]) =
                make_uint4(f2tf(a_reg[rr].x), f2tf(a_reg[rr].y), f2tf(a_reg[rr].z), f2tf(a_reg[rr].w));
        }
        #pragma unroll
        for (int kk = 0; kk < 4; kk++) {
            const int kidx = b_dr + kk * 8;
            Bs[b_ln4 + 0][kidx] = f2tf(b_reg[kk].x);
            Bs[b_ln4 + 1][kidx] = f2tf(b_reg[kk].y);
            Bs[b_ln4 + 2][kidx] = f2tf(b_reg[kk].z);
            Bs[b_ln4 + 3][kidx] = f2tf(b_reg[kk].w);
        }
        __syncthreads();

        const int kn = k0 + 32;
        if (kn < DMM) {
            #pragma unroll
            for (int rr = 0; rr < 4; rr++)
                a_reg[rr] = *reinterpret_cast<const float4*>(A + (size_t)(m0 + a_r + rr * 32) * DMM + kn + a_c4);
            #pragma unroll
            for (int kk = 0; kk < 4; kk++)
                b_reg[kk] = *reinterpret_cast<const float4*>(Wp + (size_t)(kn + b_dr + kk * 8) * DKK);
        }

        #pragma unroll
        for (int k8 = 0; k8 < 4; k8++) {
            const int c = k8 * 8 + qd;
            uint32_t af[4][4], bf[4][2];
            #pragma unroll
            for (int mi = 0; mi < 4; mi++) {
                const int r = warp_m + mi * 16 + grp;
                af[mi][0] = As[r][c];     af[mi][1] = As[r + 8][c];
                af[mi][2] = As[r][c + 4]; af[mi][3] = As[r + 8][c + 4];
            }
            #pragma unroll
            for (int nj = 0; nj < 4; nj++) {
                const int n = warp_n + nj * 8 + grp;
                bf[nj][0] = Bs[n][c]; bf[nj][1] = Bs[n][c + 4];
            }
            #pragma unroll
            for (int mi = 0; mi < 4; mi++)
                #pragma unroll
                for (int nj = 0; nj < 4; nj++)
                    mma8(acc[mi][nj], af[mi], bf[nj]);
        }
        __syncthreads();
    }

    #pragma unroll
    for (int mi = 0; mi < 4; mi++) {
        #pragma unroll
        for (int half = 0; half < 2; half++) {
            const int m = m0 + warp_m + mi * 16 + grp + half * 8;
            const int b = m >> 10, l = m & 1023;
            #pragma unroll
            for (int nj = 0; nj < 4; nj++) {
                const int j = n0 + warp_n + nj * 8 + 2 * qd;
                const int h = j >> 6, kc = j & 63;
                float2 r2 = make_float2(acc[mi][nj][half * 2] * oscale,
                                        acc[mi][nj][half * 2 + 1] * oscale);
                *reinterpret_cast<float2*>(O + ((size_t)(h * BB + b) * LL + l) * DKK + kc) = r2;
            }
        }
    }
}

// ===========================================================================
// Kernel 2: fused scores pass.  CTA per (m-tile, hb).  Q resident in smem,
// K streamed in 128-row chunks.  Writes E = exp(S) (masked->0) and per-row
// sums (register accumulated, one smem reduction; no atomics, no zero pass).
// Dyn smem: Qs[128][68] | Ks[128][68] | part[4][128]
// ===========================================================================
#define SC_QS 0
#define SC_KS (128*68)
#define SC_PART (SC_KS + 128*68)
#define SC_SMEM_BYTES ((SC_PART + 4*128) * 4)

__global__ __launch_bounds__(256) void scores_kernel(
    const unsigned char* __restrict__ mask, float* __restrict__ attn_out)
{
    extern __shared__ uint32_t dsm[];
    uint32_t* Qs = dsm + SC_QS;              // [128][68]
    uint32_t* Ks = dsm + SC_KS;              // [128][68]
    float* part = (float*)(dsm + SC_PART);   // [4][128]

    const int m0 = blockIdx.x * 128;
    const int hb = blockIdx.y;
    const int b = hb & (BB - 1);
    const float* Qp = g_qs + (size_t)hb * LL * DKK;
    const float* Kp = g_ks + (size_t)hb * LL * DKK;
    float* E = attn_out + (size_t)hb * LL * LL;

    const int tid = threadIdx.x;
    const int wid = tid >> 5, lane = tid & 31;
    const int warp_m = (wid & 1) * 64;
    const int warp_n = (wid >> 1) * 32;
    const int grp = lane >> 2, qd = lane & 3;

    // load Q tile resident (128 x 64), tf32
    #pragma unroll
    for (int j = 0; j < 8; j++) {
        const int idx = tid + 256 * j;
        const int r = idx >> 4, c4 = (idx & 15) * 4;
        float4 qv = *reinterpret_cast<const float4*>(Qp + (size_t)(m0 + r) * DKK + c4);
        *reinterpret_cast<uint4*>(&Qs[r * 68 + c4]) =
            make_uint4(f2tf(qv.x), f2tf(qv.y), f2tf(qv.z), f2tf(qv.w));
    }

    float rowacc[4][2];
    #pragma unroll
    for (int i = 0; i < 4; i++) { rowacc[i][0] = 0.0f; rowacc[i][1] = 0.0f; }

    for (int n0c = 0; n0c < LL; n0c += 128) {
        __syncthreads();
        #pragma unroll
        for (int j = 0; j < 8; j++) {
            const int idx = tid + 256 * j;
            const int r = idx >> 4, c4 = (idx & 15) * 4;
            float4 kv = *reinterpret_cast<const float4*>(Kp + (size_t)(n0c + r) * DKK + c4);
            *reinterpret_cast<uint4*>(&Ks[r * 68 + c4]) =
                make_uint4(f2tf(kv.x), f2tf(kv.y), f2tf(kv.z), f2tf(kv.w));
        }
        __syncthreads();

        float acc[4][4][4];
        #pragma unroll
        for (int i = 0; i < 4; i++)
            #pragma unroll
            for (int j = 0; j < 4; j++)
                #pragma unroll
                for (int e = 0; e < 4; e++) acc[i][j][e] = 0.0f;

        #pragma unroll
        for (int k8 = 0; k8 < 8; k8++) {
            const int c = k8 * 8 + qd;
            uint32_t af[4][4], bf[4][2];
            #pragma unroll
            for (int mi = 0; mi < 4; mi++) {
                const int r = warp_m + mi * 16 + grp;
                af[mi][0] = Qs[r * 68 + c];       af[mi][1] = Qs[(r + 8) * 68 + c];
                af[mi][2] = Qs[r * 68 + c + 4];   af[mi][3] = Qs[(r + 8) * 68 + c + 4];
            }
            #pragma unroll
            for (int nj = 0; nj < 4; nj++) {
                const int n = warp_n + nj * 8 + grp;
                bf[nj][0] = Ks[n * 68 + c]; bf[nj][1] = Ks[n * 68 + c + 4];
            }
            #pragma unroll
            for (int mi = 0; mi < 4; mi++)
                #pragma unroll
                for (int nj = 0; nj < 4; nj++)
                    mma8(acc[mi][nj], af[mi], bf[nj]);
        }

        // epilogue: exp, mask, write E, accumulate rowsums in regs
        #pragma unroll
        for (int mi = 0; mi < 4; mi++) {
            #pragma unroll
            for (int half = 0; half < 2; half++) {
                const int gi = m0 + warp_m + mi * 16 + grp + half * 8;
                const unsigned char* mrow = mask + (size_t)b * LL * LL + (size_t)gi * LL;
                float* erow = E + (size_t)gi * LL;
                float rp = 0.0f;
                #pragma unroll
                for (int nj = 0; nj < 4; nj++) {
                    const int gj = n0c + warp_n + nj * 8 + 2 * qd;
                    float e0 = mrow[gj + 0] ? 0.0f : __expf(acc[mi][nj][half * 2]);
                    float e1 = mrow[gj + 1] ? 0.0f : __expf(acc[mi][nj][half * 2 + 1]);
                    *reinterpret_cast<float2*>(erow + gj) = make_float2(e0, e1);
                    rp += e0 + e1;
                }
                rowacc[mi][half] += rp;
            }
        }
    }

    // reduce over quad lanes, stash per-(n-warp-group) partials, final sum
    #pragma unroll
    for (int mi = 0; mi < 4; mi++) {
        #pragma unroll
        for (int half = 0; half < 2; half++) {
            float v0 = rowacc[mi][half];
            v0 += __shfl_xor_sync(0xffffffffu, v0, 1);
            v0 += __shfl_xor_sync(0xffffffffu, v0, 2);
            if (qd == 0)
                part[(wid >> 1) * 128 + warp_m + mi * 16 + grp + half * 8] = v0;
        }
    }
    __syncthreads();
    if (tid < 128)
        g_rowsum[(size_t)hb * LL + m0 + tid] =
            part[tid] + part[128 + tid] + part[256 + tid] + part[384 + tid];
}

// ===========================================================================
// Kernel 3: normalize P in-place + ctx = P @ V (tf32 MMA, R2-style loads)
// ===========================================================================
__global__ __launch_bounds__(256) void pv_kernel(float* __restrict__ attn)
{
    const int hb = blockIdx.y;
    const int h = hb >> 3, b = hb & (BB - 1);
    float* P = attn + (size_t)hb * LL * LL;
    const float* V = g_vs + (size_t)hb * LL * DKK;

    __shared__ uint32_t As[128][36];
    __shared__ uint32_t Bv[32][72];   // [k][n]

    const int m0 = blockIdx.x * 128;
    const int tid = threadIdx.x;
    const int wid = tid >> 5, lane = tid & 31;
    const int warp_m = (wid & 3) * 32;
    const int warp_n = (wid >> 2) * 32;
    const int grp = lane >> 2, qd = lane & 3;

    const int a_r = tid >> 3;           // 0..31
    const int a_c4 = (tid & 7) * 4;     // 0..28
    const int v_k = tid >> 4;           // 0..15
    const int v_c4 = (tid & 15) * 4;    // 0..60

    float inv_r[4];
    #pragma unroll
    for (int rr = 0; rr < 4; rr++)
        inv_r[rr] = 1.0f / g_rowsum[(size_t)hb * LL + m0 + a_r + rr * 32];

    float acc[2][4][4];
    #pragma unroll
    for (int i = 0; i < 2; i++)
        #pragma unroll
        for (int j = 0; j < 4; j++)
            #pragma unroll
            for (int e = 0; e < 4; e++) acc[i][j][e] = 0.0f;

    for (int k0 = 0; k0 < LL; k0 += 32) {
        #pragma unroll
        for (int rr = 0; rr < 4; rr++) {
            const int r = a_r + rr * 32;
            float4 e = *reinterpret_cast<const float4*>(P + (size_t)(m0 + r) * LL + k0 + a_c4);
            e.x *= inv_r[rr]; e.y *= inv_r[rr]; e.z *= inv_r[rr]; e.w *= inv_r[rr];
            *reinterpret_cast<float4*>(P + (size_t)(m0 + r) * LL + k0 + a_c4) = e;
            *reinterpret_cast<uint4*>(&As[r][a_c4]) =
                make_uint4(f2tf(e.x), f2tf(e.y), f2tf(e.z), f2tf(e.w));
        }
        #pragma unroll
        for (int kk = 0; kk < 2; kk++) {
            const int kr = v_k + kk * 16;
            float4 bv = *reinterpret_cast<const float4*>(V + (size_t)(k0 + kr) * DKK + v_c4);
            *reinterpret_cast<uint4*>(&Bv[kr][v_c4]) =
                make_uint4(f2tf(bv.x), f2tf(bv.y), f2tf(bv.z), f2tf(bv.w));
        }
        __syncthreads();

        #pragma unroll
        for (int k8 = 0; k8 < 4; k8++) {
            const int c = k8 * 8 + qd;
            uint32_t af[2][4], bf[4][2];
            #pragma unroll
            for (int mi = 0; mi < 2; mi++) {
                const int r = warp_m + mi * 16 + grp;
                af[mi][0] = As[r][c];     af[mi][1] = As[r + 8][c];
                af[mi][2] = As[r][c + 4]; af[mi][3] = As[r + 8][c + 4];
            }
            #pragma unroll
            for (int nj = 0; nj < 4; nj++) {
                const int n = warp_n + nj * 8 + grp;
                bf[nj][0] = Bv[c][n]; bf[nj][1] = Bv[c + 4][n];
            }
            #pragma unroll
            for (int mi = 0; mi < 2; mi++)
                #pragma unroll
                for (int nj = 0; nj < 4; nj++)
                    mma8(acc[mi][nj], af[mi], bf[nj]);
        }
        __syncthreads();
    }

    #pragma unroll
    for (int mi = 0; mi < 2; mi++) {
        #pragma unroll
        for (int half = 0; half < 2; half++) {
            const int m = m0 + warp_m + mi * 16 + grp + half * 8;
            #pragma unroll
            for (int nj = 0; nj < 4; nj++) {
                const int col = warp_n + nj * 8 + 2 * qd;
                float2 r2 = make_float2(acc[mi][nj][half * 2], acc[mi][nj][half * 2 + 1]);
                *reinterpret_cast<float2*>(
                    g_ctx + ((size_t)b * LL + m) * DMM + h * DKK + col) = r2;
            }
        }
    }
}

// ===========================================================================
// Kernel 4: out = ctx @ proj_w^T + bias + residual (tf32 MMA, reg-prefetch)
// ===========================================================================
__global__ __launch_bounds__(256) void proj_kernel(
    const float* __restrict__ pw, const float* __restrict__ pb,
    const float* __restrict__ resid)
{
    __shared__ uint32_t As[128][36];
    __shared__ uint32_t Bs[128][36];

    const int m0 = blockIdx.x * 128;
    const int n0 = blockIdx.y * 128;
    const int tid = threadIdx.x;
    const int wid = tid >> 5, lane = tid & 31;
    const int warp_m = (wid & 1) * 64;
    const int warp_n = (wid >> 1) * 32;
    const int grp = lane >> 2, qd = lane & 3;

    const int a_r = tid >> 3;
    const int a_c4 = (tid & 7) * 4;

    float acc[4][4][4];
    #pragma unroll
    for (int i = 0; i < 4; i++)
        #pragma unroll
        for (int j = 0; j < 4; j++)
            #pragma unroll
            for (int e = 0; e < 4; e++) acc[i][j][e] = 0.0f;

    float4 a_reg[4], b_reg[4];
    #pragma unroll
    for (int rr = 0; rr < 4; rr++) {
        a_reg[rr] = *reinterpret_cast<const float4*>(g_ctx + (size_t)(m0 + a_r + rr * 32) * DMM + a_c4);
        b_reg[rr] = *reinterpret_cast<const float4*>(pw + (size_t)(n0 + a_r + rr * 32) * DMM + a_c4);
    }

    for (int k0 = 0; k0 < DMM; k0 += 32) {
        #pragma unroll
        for (int rr = 0; rr < 4; rr++) {
            const int r = a_r + rr * 32;
            *reinterpret_cast<uint4*>(&As[r][a_c4]) =
                make_uint4(f2tf(a_reg[rr].x), f2tf(a_reg[rr].y), f2tf(a_reg[rr].z), f2tf(a_reg[rr].w));
            *reinterpret_cast<uint4*>(&Bs[r][a_c4]) =
                make_uint4(f2tf(b_reg[rr].x), f2tf(b_reg[rr].y), f2tf(b_reg[rr].z), f2tf(b_reg[rr].w));
        }
        __syncthreads();

        const int kn = k0 + 32;
        if (kn < DMM) {
            #pragma unroll
            for (int rr = 0; rr < 4; rr++) {
                a_reg[rr] = *reinterpret_cast<const float4*>(g_ctx + (size_t)(m0 + a_r + rr * 32) * DMM + kn + a_c4);
                b_reg[rr] = *reinterpret_cast<const float4*>(pw + (size_t)(n0 + a_r + rr * 32) * DMM + kn + a_c4);
            }
        }

        #pragma unroll
        for (int k8 = 0; k8 < 4; k8++) {
            const int c = k8 * 8 + qd;
            uint32_t af[4][4], bf[4][2];
            #pragma unroll
            for (int mi = 0; mi < 4; mi++) {
                const int r = warp_m + mi * 16 + grp;
                af[mi][0] = As[r][c];     af[mi][1] = As[r + 8][c];
                af[mi][2] = As[r][c + 4]; af[mi][3] = As[r + 8][c + 4];
            }
            #pragma unroll
            for (int nj = 0; nj < 4; nj++) {
                const int n = warp_n + nj * 8 + grp;
                bf[nj][0] = Bs[n][c]; bf[nj][1] = Bs[n][c + 4];
            }
            #pragma unroll
            for (int mi = 0; mi < 4; mi++)
                #pragma unroll
                for (int nj = 0; nj < 4; nj++)
                    mma8(acc[mi][nj], af[mi], bf[nj]);
        }
        __syncthreads();
    }

    #pragma unroll
    for (int mi = 0; mi < 4; mi++) {
        #pragma unroll
        for (int half = 0; half < 2; half++) {
            const int m = m0 + warp_m + mi * 16 + grp + half * 8;
            #pragma unroll
            for (int nj = 0; nj < 4; nj++) {
                const int j = n0 + warp_n + nj * 8 + 2 * qd;
                float2 bias = *reinterpret_cast<const float2*>(pb + j);
                float2 rq = *reinterpret_cast<const float2*>(resid + (size_t)m * DMM + j);
                float2 r2 = make_float2(acc[mi][nj][half * 2] + bias.x + rq.x,
                                        acc[mi][nj][half * 2 + 1] + bias.y + rq.y);
                *reinterpret_cast<float2*>(g_tmp + (size_t)m * DMM + j) = r2;
            }
        }
    }
}

// ===========================================================================
// Kernel 5: LayerNorm
// ===========================================================================
__global__ __launch_bounds__(256) void ln_kernel(
    const float* __restrict__ gamma, const float* __restrict__ beta,
    float* __restrict__ out)
{
    const float* p = g_tmp + (size_t)blockIdx.x * DMM;
    float* o = out + (size_t)blockIdx.x * DMM;
    const int tid = threadIdx.x;
    float4 x = reinterpret_cast<const float4*>(p)[tid];

    float s = x.x + x.y + x.z + x.w;
    float sq = x.x * x.x + x.y * x.y + x.z * x.z + x.w * x.w;
    #pragma unroll
    for (int off = 16; off > 0; off >>= 1) {
        s += __shfl_xor_sync(0xffffffffu, s, off);
        sq += __shfl_xor_sync(0xffffffffu, sq, off);
    }
    __shared__ float s1[8], s2[8];
    if ((tid & 31) == 0) { s1[tid >> 5] = s; s2[tid >> 5] = sq; }
    __syncthreads();
    float ts = 0.0f, tsq = 0.0f;
    #pragma unroll
    for (int i = 0; i < 8; i++) { ts += s1[i]; tsq += s2[i]; }
    const float mean = ts * (1.0f / DMM);
    const float var = tsq * (1.0f / DMM) - mean * mean;
    const float inv = rsqrtf(var + 1e-5f);

    float4 g = reinterpret_cast<const float4*>(gamma)[tid];
    float4 be = reinterpret_cast<const float4*>(beta)[tid];
    float4 r;
    r.x = (x.x - mean) * inv * g.x + be.x;
    r.y = (x.y - mean) * inv * g.y + be.y;
    r.z = (x.z - mean) * inv * g.z + be.z;
    r.w = (x.w - mean) * inv * g.w + be.w;
    reinterpret_cast<float4*>(o)[tid] = r;
}

// ---------------------------------------------------------------------------
extern "C" void kernel_launch(void* const* d_in, const int* in_sizes, int n_in,
                              void* d_out, int out_size)
{
    const float* q  = (const float*)d_in[0];
    const float* k  = (const float*)d_in[1];
    const float* v  = (const float*)d_in[2];
    const unsigned char* mask = (const unsigned char*)d_in[3];
    const float* wq = (const float*)d_in[4];
    const float* wk = (const float*)d_in[5];
    const float* wv = (const float*)d_in[6];
    const float* pw = (const float*)d_in[7];
    const float* pb = (const float*)d_in[8];
    const float* ga = (const float*)d_in[9];
    const float* be = (const float*)d_in[10];

    float* out = (float*)d_out;
    float* attn = out + ATTN_OFF;

    cudaFuncSetAttribute(scores_kernel, cudaFuncAttributeMaxDynamicSharedMemorySize, SC_SMEM_BYTES);

    qkv_kernel<<<dim3(BL / 128, DMM / 128, 3), 256>>>(q, k, v, wq, wk, wv);
    scores_kernel<<<dim3(LL / 128, HBC), 256, SC_SMEM_BYTES>>>(mask, attn);
    pv_kernel<<<dim3(LL / 128, HBC), 256>>>(attn);
    proj_kernel<<<dim3(BL / 128, DMM / 128), 256>>>(pw, pb, q);
    ln_kernel<<<dim3(BL), 256>>>(ga, be, out);
}

// round 7
// speedup vs baseline: 1.0836x; 1.0836x over previous
#include <cuda_runtime.h>
#include <math.h>
#include <stdint.h>

// Problem constants
#define BB 8
#define LL 1024
#define HH 16
#define DKK 64
#define DMM 1024
#define BL (BB*LL)          // 8192
#define HBC (HH*BB)         // 128
#define ATTN_OFF ((size_t)BL*DMM)

// Scratch
__device__ float g_qs[(size_t)HBC*LL*DKK];   // (h*B+b, l, dk), q pre-scaled 1/32
__device__ float g_ks[(size_t)HBC*LL*DKK];
__device__ float g_vs[(size_t)HBC*LL*DKK];
__device__ float g_ctx[(size_t)BL*DMM];
__device__ float g_tmp[(size_t)BL*DMM];
__device__ float g_rowsum[(size_t)HBC*LL];

// ---------------------------------------------------------------------------
__device__ __forceinline__ uint32_t f2tf(float f) {
    uint32_t u;
    asm("cvt.rna.tf32.f32 %0, %1;" : "=r"(u) : "f"(f));
    return u;
}

__device__ __forceinline__ void mma8(float* c, const uint32_t* a, const uint32_t* b) {
    asm volatile(
        "mma.sync.aligned.m16n8k8.row.col.f32.tf32.tf32.f32 "
        "{%0,%1,%2,%3},{%4,%5,%6,%7},{%8,%9},{%0,%1,%2,%3};\n"
        : "+f"(c[0]), "+f"(c[1]), "+f"(c[2]), "+f"(c[3])
        : "r"(a[0]), "r"(a[1]), "r"(a[2]), "r"(a[3]), "r"(b[0]), "r"(b[1]));
}

// ===========================================================================
// Kernel 0: zero row sums
// ===========================================================================
__global__ void zero_rowsum_kernel() {
    g_rowsum[blockIdx.x * 256 + threadIdx.x] = 0.0f;
}

// ===========================================================================
// Kernel 1: QKV projection (tf32 MMA, reg-prefetch double buffering)
// ===========================================================================
__global__ __launch_bounds__(256) void qkv_kernel(
    const float* __restrict__ q, const float* __restrict__ k, const float* __restrict__ v,
    const float* __restrict__ wq, const float* __restrict__ wk, const float* __restrict__ wv)
{
    const int which = blockIdx.z;
    const float* A = (which == 0) ? q : (which == 1) ? k : v;
    const float* W = (which == 0) ? wq : (which == 1) ? wk : wv;
    float* O = (which == 0) ? g_qs : (which == 1) ? g_ks : g_vs;
    const float oscale = (which == 0) ? (1.0f / 32.0f) : 1.0f;

    __shared__ uint32_t As[128][36];
    __shared__ uint32_t Bs[128][36];

    const int m0 = blockIdx.x * 128;
    const int n0 = blockIdx.y * 128;
    const int tid = threadIdx.x;
    const int wid = tid >> 5, lane = tid & 31;
    const int warp_m = (wid & 1) * 64;
    const int warp_n = (wid >> 1) * 32;
    const int grp = lane >> 2, qd = lane & 3;

    const int a_r = tid >> 3;
    const int a_c4 = (tid & 7) * 4;
    const int b_ln4 = (tid & 31) * 4;
    const int b_dr = tid >> 5;
    const int b_h = (n0 + b_ln4) >> 6;
    const int b_kc4 = (n0 + b_ln4) & 63;
    const float* Wp = W + (size_t)b_h * DMM * DKK + b_kc4;

    float acc[4][4][4];
    #pragma unroll
    for (int i = 0; i < 4; i++)
        #pragma unroll
        for (int j = 0; j < 4; j++)
            #pragma unroll
            for (int e = 0; e < 4; e++) acc[i][j][e] = 0.0f;

    float4 a_reg[4], b_reg[4];
    #pragma unroll
    for (int rr = 0; rr < 4; rr++)
        a_reg[rr] = *reinterpret_cast<const float4*>(A + (size_t)(m0 + a_r + rr * 32) * DMM + a_c4);
    #pragma unroll
    for (int kk = 0; kk < 4; kk++)
        b_reg[kk] = *reinterpret_cast<const float4*>(Wp + (size_t)(b_dr + kk * 8) * DKK);

    for (int k0 = 0; k0 < DMM; k0 += 32) {
        #pragma unroll
        for (int rr = 0; rr < 4; rr++) {
            const int r = a_r + rr * 32;
            *reinterpret_cast<uint4*>(&As[r][a_c4]) =
                make_uint4(f2tf(a_reg[rr].x), f2tf(a_reg[rr].y), f2tf(a_reg[rr].z), f2tf(a_reg[rr].w));
        }
        #pragma unroll
        for (int kk = 0; kk < 4; kk++) {
            const int kidx = b_dr + kk * 8;
            Bs[b_ln4 + 0][kidx] = f2tf(b_reg[kk].x);
            Bs[b_ln4 + 1][kidx] = f2tf(b_reg[kk].y);
            Bs[b_ln4 + 2][kidx] = f2tf(b_reg[kk].z);
            Bs[b_ln4 + 3][kidx] = f2tf(b_reg[kk].w);
        }
        __syncthreads();

        const int kn = k0 + 32;
        if (kn < DMM) {
            #pragma unroll
            for (int rr = 0; rr < 4; rr++)
                a_reg[rr] = *reinterpret_cast<const float4*>(A + (size_t)(m0 + a_r + rr * 32) * DMM + kn + a_c4);
            #pragma unroll
            for (int kk = 0; kk < 4; kk++)
                b_reg[kk] = *reinterpret_cast<const float4*>(Wp + (size_t)(kn + b_dr + kk * 8) * DKK);
        }

        #pragma unroll
        for (int k8 = 0; k8 < 4; k8++) {
            const int c = k8 * 8 + qd;
            uint32_t af[4][4], bf[4][2];
            #pragma unroll
            for (int mi = 0; mi < 4; mi++) {
                const int r = warp_m + mi * 16 + grp;
                af[mi][0] = As[r][c];     af[mi][1] = As[r + 8][c];
                af[mi][2] = As[r][c + 4]; af[mi][3] = As[r + 8][c + 4];
            }
            #pragma unroll
            for (int nj = 0; nj < 4; nj++) {
                const int n = warp_n + nj * 8 + grp;
                bf[nj][0] = Bs[n][c]; bf[nj][1] = Bs[n][c + 4];
            }
            #pragma unroll
            for (int mi = 0; mi < 4; mi++)
                #pragma unroll
                for (int nj = 0; nj < 4; nj++)
                    mma8(acc[mi][nj], af[mi], bf[nj]);
        }
        __syncthreads();
    }

    #pragma unroll
    for (int mi = 0; mi < 4; mi++) {
        #pragma unroll
        for (int half = 0; half < 2; half++) {
            const int m = m0 + warp_m + mi * 16 + grp + half * 8;
            const int b = m >> 10, l = m & 1023;
            #pragma unroll
            for (int nj = 0; nj < 4; nj++) {
                const int j = n0 + warp_n + nj * 8 + 2 * qd;
                const int h = j >> 6, kc = j & 63;
                float2 r2 = make_float2(acc[mi][nj][half * 2] * oscale,
                                        acc[mi][nj][half * 2 + 1] * oscale);
                *reinterpret_cast<float2*>(O + ((size_t)(h * BB + b) * LL + l) * DKK + kc) = r2;
            }
        }
    }
}

// ===========================================================================
// Kernel 2: scores -> E = exp(S) (masked -> 0), write E, atomic row sums.
// ===========================================================================
__global__ __launch_bounds__(256) void scores_kernel(
    const unsigned char* __restrict__ mask, float* __restrict__ attn_out)
{
    const int hb = blockIdx.z;
    const int b = hb & (BB - 1);
    const float* Qp = g_qs + (size_t)hb * LL * DKK;
    const float* Kp = g_ks + (size_t)hb * LL * DKK;

    __shared__ uint32_t As[128][36];
    __shared__ uint32_t Bs[128][36];

    const int m0 = blockIdx.x * 128;
    const int n0 = blockIdx.y * 128;
    const int tid = threadIdx.x;
    const int wid = tid >> 5, lane = tid & 31;
    const int warp_m = (wid & 1) * 64;
    const int warp_n = (wid >> 1) * 32;
    const int grp = lane >> 2, qd = lane & 3;

    const int a_r = tid >> 3;
    const int a_c4 = (tid & 7) * 4;

    float acc[4][4][4];
    #pragma unroll
    for (int i = 0; i < 4; i++)
        #pragma unroll
        for (int j = 0; j < 4; j++)
            #pragma unroll
            for (int e = 0; e < 4; e++) acc[i][j][e] = 0.0f;

    for (int k0 = 0; k0 < DKK; k0 += 32) {
        __syncthreads();
        #pragma unroll
        for (int rr = 0; rr < 4; rr++) {
            const int r = a_r + rr * 32;
            float4 av = *reinterpret_cast<const float4*>(Qp + (size_t)(m0 + r) * DKK + k0 + a_c4);
            *reinterpret_cast<uint4*>(&As[r][a_c4]) =
                make_uint4(f2tf(av.x), f2tf(av.y), f2tf(av.z), f2tf(av.w));
            float4 bv = *reinterpret_cast<const float4*>(Kp + (size_t)(n0 + r) * DKK + k0 + a_c4);
            *reinterpret_cast<uint4*>(&Bs[r][a_c4]) =
                make_uint4(f2tf(bv.x), f2tf(bv.y), f2tf(bv.z), f2tf(bv.w));
        }
        __syncthreads();

        #pragma unroll
        for (int k8 = 0; k8 < 4; k8++) {
            const int c = k8 * 8 + qd;
            uint32_t af[4][4], bf[4][2];
            #pragma unroll
            for (int mi = 0; mi < 4; mi++) {
                const int r = warp_m + mi * 16 + grp;
                af[mi][0] = As[r][c];     af[mi][1] = As[r + 8][c];
                af[mi][2] = As[r][c + 4]; af[mi][3] = As[r + 8][c + 4];
            }
            #pragma unroll
            for (int nj = 0; nj < 4; nj++) {
                const int n = warp_n + nj * 8 + grp;
                bf[nj][0] = Bs[n][c]; bf[nj][1] = Bs[n][c + 4];
            }
            #pragma unroll
            for (int mi = 0; mi < 4; mi++)
                #pragma unroll
                for (int nj = 0; nj < 4; nj++)
                    mma8(acc[mi][nj], af[mi], bf[nj]);
        }
    }

    #pragma unroll
    for (int mi = 0; mi < 4; mi++) {
        #pragma unroll
        for (int half = 0; half < 2; half++) {
            const int gi = m0 + warp_m + mi * 16 + grp + half * 8;
            const unsigned char* mrow = mask + (size_t)b * LL * LL + (size_t)gi * LL;
            float* orow = attn_out + ((size_t)hb * LL + gi) * LL;
            float rowpart = 0.0f;
            #pragma unroll
            for (int nj = 0; nj < 4; nj++) {
                const int gj = n0 + warp_n + nj * 8 + 2 * qd;
                float e0 = mrow[gj + 0] ? 0.0f : __expf(acc[mi][nj][half * 2]);
                float e1 = mrow[gj + 1] ? 0.0f : __expf(acc[mi][nj][half * 2 + 1]);
                *reinterpret_cast<float2*>(orow + gj) = make_float2(e0, e1);
                rowpart += e0 + e1;
            }
            rowpart += __shfl_xor_sync(0xffffffffu, rowpart, 1);
            rowpart += __shfl_xor_sync(0xffffffffu, rowpart, 2);
            if (qd == 0) atomicAdd(&g_rowsum[(size_t)hb * LL + gi], rowpart);
        }
    }
}

// ===========================================================================
// Kernel 3: normalize P in-place + ctx = P @ V (tf32 MMA, plain loads)
// ===========================================================================
__global__ __launch_bounds__(256) void pv_kernel(float* __restrict__ attn)
{
    const int hb = blockIdx.y;
    const int h = hb >> 3, b = hb & (BB - 1);
    float* P = attn + (size_t)hb * LL * LL;
    const float* V = g_vs + (size_t)hb * LL * DKK;

    __shared__ uint32_t As[128][36];
    __shared__ uint32_t Bv[32][72];   // [k][n]

    const int m0 = blockIdx.x * 128;
    const int tid = threadIdx.x;
    const int wid = tid >> 5, lane = tid & 31;
    const int warp_m = (wid & 3) * 32;
    const int warp_n = (wid >> 2) * 32;
    const int grp = lane >> 2, qd = lane & 3;

    const int a_r = tid >> 3;           // 0..31
    const int a_c4 = (tid & 7) * 4;     // 0..28
    const int v_k = tid >> 4;           // 0..15
    const int v_c4 = (tid & 15) * 4;    // 0..60

    float inv_r[4];
    #pragma unroll
    for (int rr = 0; rr < 4; rr++)
        inv_r[rr] = 1.0f / g_rowsum[(size_t)hb * LL + m0 + a_r + rr * 32];

    float acc[2][4][4];
    #pragma unroll
    for (int i = 0; i < 2; i++)
        #pragma unroll
        for (int j = 0; j < 4; j++)
            #pragma unroll
            for (int e = 0; e < 4; e++) acc[i][j][e] = 0.0f;

    for (int k0 = 0; k0 < LL; k0 += 32) {
        #pragma unroll
        for (int rr = 0; rr < 4; rr++) {
            const int r = a_r + rr * 32;
            float4 e = *reinterpret_cast<const float4*>(P + (size_t)(m0 + r) * LL + k0 + a_c4);
            e.x *= inv_r[rr]; e.y *= inv_r[rr]; e.z *= inv_r[rr]; e.w *= inv_r[rr];
            *reinterpret_cast<float4*>(P + (size_t)(m0 + r) * LL + k0 + a_c4) = e;
            *reinterpret_cast<uint4*>(&As[r][a_c4]) =
                make_uint4(f2tf(e.x), f2tf(e.y), f2tf(e.z), f2tf(e.w));
        }
        #pragma unroll
        for (int kk = 0; kk < 2; kk++) {
            const int kr = v_k + kk * 16;
            float4 bv = *reinterpret_cast<const float4*>(V + (size_t)(k0 + kr) * DKK + v_c4);
            *reinterpret_cast<uint4*>(&Bv[kr][v_c4]) =
                make_uint4(f2tf(bv.x), f2tf(bv.y), f2tf(bv.z), f2tf(bv.w));
        }
        __syncthreads();

        #pragma unroll
        for (int k8 = 0; k8 < 4; k8++) {
            const int c = k8 * 8 + qd;
            uint32_t af[2][4], bf[4][2];
            #pragma unroll
            for (int mi = 0; mi < 2; mi++) {
                const int r = warp_m + mi * 16 + grp;
                af[mi][0] = As[r][c];     af[mi][1] = As[r + 8][c];
                af[mi][2] = As[r][c + 4]; af[mi][3] = As[r + 8][c + 4];
            }
            #pragma unroll
            for (int nj = 0; nj < 4; nj++) {
                const int n = warp_n + nj * 8 + grp;
                bf[nj][0] = Bv[c][n]; bf[nj][1] = Bv[c + 4][n];
            }
            #pragma unroll
            for (int mi = 0; mi < 2; mi++)
                #pragma unroll
                for (int nj = 0; nj < 4; nj++)
                    mma8(acc[mi][nj], af[mi], bf[nj]);
        }
        __syncthreads();
    }

    #pragma unroll
    for (int mi = 0; mi < 2; mi++) {
        #pragma unroll
        for (int half = 0; half < 2; half++) {
            const int m = m0 + warp_m + mi * 16 + grp + half * 8;
            #pragma unroll
            for (int nj = 0; nj < 4; nj++) {
                const int col = warp_n + nj * 8 + 2 * qd;
                float2 r2 = make_float2(acc[mi][nj][half * 2], acc[mi][nj][half * 2 + 1]);
                *reinterpret_cast<float2*>(
                    g_ctx + ((size_t)b * LL + m) * DMM + h * DKK + col) = r2;
            }
        }
    }
}

// ===========================================================================
// Kernel 4: out = ctx @ proj_w^T + bias + residual (tf32 MMA, reg-prefetch)
// ===========================================================================
__global__ __launch_bounds__(256) void proj_kernel(
    const float* __restrict__ pw, const float* __restrict__ pb,
    const float* __restrict__ resid)
{
    __shared__ uint32_t As[128][36];
    __shared__ uint32_t Bs[128][36];

    const int m0 = blockIdx.x * 128;
    const int n0 = blockIdx.y * 128;
    const int tid = threadIdx.x;
    const int wid = tid >> 5, lane = tid & 31;
    const int warp_m = (wid & 1) * 64;
    const int warp_n = (wid >> 1) * 32;
    const int grp = lane >> 2, qd = lane & 3;

    const int a_r = tid >> 3;
    const int a_c4 = (tid & 7) * 4;

    float acc[4][4][4];
    #pragma unroll
    for (int i = 0; i < 4; i++)
        #pragma unroll
        for (int j = 0; j < 4; j++)
            #pragma unroll
            for (int e = 0; e < 4; e++) acc[i][j][e] = 0.0f;

    float4 a_reg[4], b_reg[4];
    #pragma unroll
    for (int rr = 0; rr < 4; rr++) {
        a_reg[rr] = *reinterpret_cast<const float4*>(g_ctx + (size_t)(m0 + a_r + rr * 32) * DMM + a_c4);
        b_reg[rr] = *reinterpret_cast<const float4*>(pw + (size_t)(n0 + a_r + rr * 32) * DMM + a_c4);
    }

    for (int k0 = 0; k0 < DMM; k0 += 32) {
        #pragma unroll
        for (int rr = 0; rr < 4; rr++) {
            const int r = a_r + rr * 32;
            *reinterpret_cast<uint4*>(&As[r][a_c4]) =
                make_uint4(f2tf(a_reg[rr].x), f2tf(a_reg[rr].y), f2tf(a_reg[rr].z), f2tf(a_reg[rr].w));
            *reinterpret_cast<uint4*>(&Bs[r][a_c4]) =
                make_uint4(f2tf(b_reg[rr].x), f2tf(b_reg[rr].y), f2tf(b_reg[rr].z), f2tf(b_reg[rr].w));
        }
        __syncthreads();

        const int kn = k0 + 32;
        if (kn < DMM) {
            #pragma unroll
            for (int rr = 0; rr < 4; rr++) {
                a_reg[rr] = *reinterpret_cast<const float4*>(g_ctx + (size_t)(m0 + a_r + rr * 32) * DMM + kn + a_c4);
                b_reg[rr] = *reinterpret_cast<const float4*>(pw + (size_t)(n0 + a_r + rr * 32) * DMM + kn + a_c4);
            }
        }

        #pragma unroll
        for (int k8 = 0; k8 < 4; k8++) {
            const int c = k8 * 8 + qd;
            uint32_t af[4][4], bf[4][2];
            #pragma unroll
            for (int mi = 0; mi < 4; mi++) {
                const int r = warp_m + mi * 16 + grp;
                af[mi][0] = As[r][c];     af[mi][1] = As[r + 8][c];
                af[mi][2] = As[r][c + 4]; af[mi][3] = As[r + 8][c + 4];
            }
            #pragma unroll
            for (int nj = 0; nj < 4; nj++) {
                const int n = warp_n + nj * 8 + grp;
                bf[nj][0] = Bs[n][c]; bf[nj][1] = Bs[n][c + 4];
            }
            #pragma unroll
            for (int mi = 0; mi < 4; mi++)
                #pragma unroll
                for (int nj = 0; nj < 4; nj++)
                    mma8(acc[mi][nj], af[mi], bf[nj]);
        }
        __syncthreads();
    }

    #pragma unroll
    for (int mi = 0; mi < 4; mi++) {
        #pragma unroll
        for (int half = 0; half < 2; half++) {
            const int m = m0 + warp_m + mi * 16 + grp + half * 8;
            #pragma unroll
            for (int nj = 0; nj < 4; nj++) {
                const int j = n0 + warp_n + nj * 8 + 2 * qd;
                float2 bias = *reinterpret_cast<const float2*>(pb + j);
                float2 rq = *reinterpret_cast<const float2*>(resid + (size_t)m * DMM + j);
                float2 r2 = make_float2(acc[mi][nj][half * 2] + bias.x + rq.x,
                                        acc[mi][nj][half * 2 + 1] + bias.y + rq.y);
                *reinterpret_cast<float2*>(g_tmp + (size_t)m * DMM + j) = r2;
            }
        }
    }
}

// ===========================================================================
// Kernel 5: LayerNorm
// ===========================================================================
__global__ __launch_bounds__(256) void ln_kernel(
    const float* __restrict__ gamma, const float* __restrict__ beta,
    float* __restrict__ out)
{
    const float* p = g_tmp + (size_t)blockIdx.x * DMM;
    float* o = out + (size_t)blockIdx.x * DMM;
    const int tid = threadIdx.x;
    float4 x = reinterpret_cast<const float4*>(p)[tid];

    float s = x.x + x.y + x.z + x.w;
    float sq = x.x * x.x + x.y * x.y + x.z * x.z + x.w * x.w;
    #pragma unroll
    for (int off = 16; off > 0; off >>= 1) {
        s += __shfl_xor_sync(0xffffffffu, s, off);
        sq += __shfl_xor_sync(0xffffffffu, sq, off);
    }
    __shared__ float s1[8], s2[8];
    if ((tid & 31) == 0) { s1[tid >> 5] = s; s2[tid >> 5] = sq; }
    __syncthreads();
    float ts = 0.0f, tsq = 0.0f;
    #pragma unroll
    for (int i = 0; i < 8; i++) { ts += s1[i]; tsq += s2[i]; }
    const float mean = ts * (1.0f / DMM);
    const float var = tsq * (1.0f / DMM) - mean * mean;
    const float inv = rsqrtf(var + 1e-5f);

    float4 g = reinterpret_cast<const float4*>(gamma)[tid];
    float4 be = reinterpret_cast<const float4*>(beta)[tid];
    float4 r;
    r.x = (x.x - mean) * inv * g.x + be.x;
    r.y = (x.y - mean) * inv * g.y + be.y;
    r.z = (x.z - mean) * inv * g.z + be.z;
    r.w = (x.w - mean) * inv * g.w + be.w;
    reinterpret_cast<float4*>(o)[tid] = r;
}

// ---------------------------------------------------------------------------
extern "C" void kernel_launch(void* const* d_in, const int* in_sizes, int n_in,
                              void* d_out, int out_size)
{
    const float* q  = (const float*)d_in[0];
    const float* k  = (const float*)d_in[1];
    const float* v  = (const float*)d_in[2];
    const unsigned char* mask = (const unsigned char*)d_in[3];
    const float* wq = (const float*)d_in[4];
    const float* wk = (const float*)d_in[5];
    const float* wv = (const float*)d_in[6];
    const float* pw = (const float*)d_in[7];
    const float* pb = (const float*)d_in[8];
    const float* ga = (const float*)d_in[9];
    const float* be = (const float*)d_in[10];

    float* out = (float*)d_out;
    float* attn = out + ATTN_OFF;

    zero_rowsum_kernel<<<dim3(HBC * LL / 256), 256>>>();
    qkv_kernel<<<dim3(BL / 128, DMM / 128, 3), 256>>>(q, k, v, wq, wk, wv);
    scores_kernel<<<dim3(LL / 128, LL / 128, HBC), 256>>>(mask, attn);
    pv_kernel<<<dim3(LL / 128, HBC), 256>>>(attn);
    proj_kernel<<<dim3(BL / 128, DMM / 128), 256>>>(pw, pb, q);
    ln_kernel<<<dim3(BL), 256>>>(ga, be, out);
}